// round 1
// baseline (speedup 1.0000x reference)
#include <cuda_runtime.h>

#define POOLED 7
#define KSIZE  2
#define CROP   (POOLED * KSIZE)   // 14
#define HH     50
#define WW     50
#define CC     512
#define RR     128
#define BB     2
#define NROI   (BB * RR)          // 256

__device__ __forceinline__ float4 lerp4(float4 a, float4 b, float w) {
    float4 r;
    r.x = a.x + (b.x - a.x) * w;
    r.y = a.y + (b.y - a.y) * w;
    r.z = a.z + (b.z - a.z) * w;
    r.w = a.w + (b.w - a.w) * w;
    return r;
}

__global__ __launch_bounds__(128)
void roi_pool_kernel(const float* __restrict__ fm,
                     const float* __restrict__ rois,
                     float* __restrict__ out) {
    const int cell = blockIdx.x;            // 0 .. 256*49-1
    const int n  = cell / (POOLED * POOLED);
    const int pp = cell - n * (POOLED * POOLED);
    const int ph = pp / POOLED;
    const int pw = pp - ph * POOLED;
    const int b  = n >> 7;                  // n / 128

    // rois layout: (B, R, 4) -> flat n*4 + {0:x1, 1:y1, 2:x2, 3:y2} after
    // the reference's [1,0,3,2] permutation (y1=rois[...,1], x1=rois[...,0], ...)
    const float rx1 = __ldg(&rois[n * 4 + 0]);
    const float ry1 = __ldg(&rois[n * 4 + 1]);
    const float rx2 = __ldg(&rois[n * 4 + 2]);
    const float ry2 = __ldg(&rois[n * 4 + 3]);

    // match reference arithmetic: ys = y1*(H-1) + i * ((y2-y1)*(H-1)/(CROP-1))
    const float sy = (ry2 - ry1) * (float)(HH - 1) / (float)(CROP - 1);
    const float sx = (rx2 - rx1) * (float)(WW - 1) / (float)(CROP - 1);
    const float by = ry1 * (float)(HH - 1);
    const float bx = rx1 * (float)(WW - 1);

    // Per-ky (2 rows of the 2x2 crop window) y coordinates
    int   y0i[KSIZE], y1i[KSIZE];
    float wy[KSIZE];
    bool  vy[KSIZE];
#pragma unroll
    for (int ky = 0; ky < KSIZE; ky++) {
        const float i  = (float)(KSIZE * ph + ky);
        const float ys = by + i * sy;
        vy[ky] = (ys >= 0.0f) && (ys <= (float)(HH - 1));
        const float y0f = floorf(ys);
        wy[ky] = ys - y0f;
        int y0 = (int)y0f;
        y0 = min(max(y0, 0), HH - 1);
        y0i[ky] = y0;
        y1i[ky] = min(y0 + 1, HH - 1);
    }

    int   x0i[KSIZE], x1i[KSIZE];
    float wx[KSIZE];
    bool  vx[KSIZE];
#pragma unroll
    for (int kx = 0; kx < KSIZE; kx++) {
        const float j  = (float)(KSIZE * pw + kx);
        const float xs = bx + j * sx;
        vx[kx] = (xs >= 0.0f) && (xs <= (float)(WW - 1));
        const float x0f = floorf(xs);
        wx[kx] = xs - x0f;
        int x0 = (int)x0f;
        x0 = min(max(x0, 0), WW - 1);
        x0i[kx] = x0;
        x1i[kx] = min(x0 + 1, WW - 1);
    }

    const int c4 = threadIdx.x;             // channel group, 0..127 (float4)
    const float4* __restrict__ fmv = (const float4*)fm;

    // Issue all 16 loads up-front for MLP. Index: ((b*H + y)*W + x)*128 + c4
    float4 px[KSIZE][KSIZE][4];             // [ky][kx][corner: y0x0,y0x1,y1x0,y1x1]
#pragma unroll
    for (int ky = 0; ky < KSIZE; ky++) {
        const long rowBase0 = (long)((b * HH + y0i[ky]) * WW) * 128;
        const long rowBase1 = (long)((b * HH + y1i[ky]) * WW) * 128;
#pragma unroll
        for (int kx = 0; kx < KSIZE; kx++) {
            px[ky][kx][0] = fmv[rowBase0 + (long)x0i[kx] * 128 + c4];
            px[ky][kx][1] = fmv[rowBase0 + (long)x1i[kx] * 128 + c4];
            px[ky][kx][2] = fmv[rowBase1 + (long)x0i[kx] * 128 + c4];
            px[ky][kx][3] = fmv[rowBase1 + (long)x1i[kx] * 128 + c4];
        }
    }

    float4 best;
    best.x = best.y = best.z = best.w = -__FLT_MAX__;
#pragma unroll
    for (int ky = 0; ky < KSIZE; ky++) {
#pragma unroll
        for (int kx = 0; kx < KSIZE; kx++) {
            // y-interp first (reference order), then x-interp
            float4 t0 = lerp4(px[ky][kx][0], px[ky][kx][2], wy[ky]); // at x0
            float4 t1 = lerp4(px[ky][kx][1], px[ky][kx][3], wy[ky]); // at x1
            float4 v  = lerp4(t0, t1, wx[kx]);
            const bool valid = vy[ky] && vx[kx];
            if (!valid) { v.x = 0.0f; v.y = 0.0f; v.z = 0.0f; v.w = 0.0f; }
            best.x = fmaxf(best.x, v.x);
            best.y = fmaxf(best.y, v.y);
            best.z = fmaxf(best.z, v.z);
            best.w = fmaxf(best.w, v.w);
        }
    }

    ((float4*)out)[(long)cell * 128 + c4] = best;
}

extern "C" void kernel_launch(void* const* d_in, const int* in_sizes, int n_in,
                              void* d_out, int out_size) {
    const float* fm   = (const float*)d_in[0];   // (2,50,50,512) f32
    const float* rois = (const float*)d_in[1];   // (2,128,4) f32
    float* out = (float*)d_out;                  // (256,7,7,512) f32

    const int blocks = NROI * POOLED * POOLED;   // 12544
    roi_pool_kernel<<<blocks, 128>>>(fm, rois, out);
}